// round 4
// baseline (speedup 1.0000x reference)
#include <cuda_runtime.h>
#include <math.h>

#define B 64
#define T 4096
#define D 512
#define NSPLIT 16          // CTAs per batch in partial kernel
#define WARPS 8            // warps per CTA
#define NPART (NSPLIT * WARPS)   // 128 partials per batch
#define ROWS_PER_WARP 32   // T / NSPLIT / WARPS

// Scratch (static device globals: allocation-free)
__device__ float g_key[B * D];                       // 128 KB
__device__ float g_pm[B * NPART];                    // running max per partial
__device__ float g_ps[B * NPART];                    // running sum per partial
__device__ float g_pc[(size_t)B * NPART * D];        // partial context, ~16.8 MB
__device__ int   g_mask_kind;                        // 0=int32, 1=uint8, 2=float32

// ---------------------------------------------------------------------------
// Kernel 0: sniff the mask dtype from its raw bytes (deterministic).
//   int32 mask of {0,1}: every 32-bit word is 0 or 1.
//   uint8 mask of {0,1}: words have random 0/1 bytes -> some word has a byte
//                        set above byte 0 (prob of none over 8192 words ~ 8^-8192).
//   f32   mask of {0,1}: words are 0 or 0x3f800000.
// ---------------------------------------------------------------------------
__global__ void detect_mask_kernel(const unsigned int* __restrict__ mw) {
    __shared__ int s_kind;
    if (threadIdx.x == 0) s_kind = 0;
    __syncthreads();
    int kind = 0;
    for (int i = threadIdx.x; i < 8192; i += blockDim.x) {
        unsigned int w = mw[i];
        if (w == 0x3f800000u)            kind = 2;            // float 1.0f
        else if ((w & 0xFFFFFF00u) != 0) kind = (kind == 2) ? 2 : 1; // high byte set
    }
    if (kind) atomicMax(&s_kind, kind);
    __syncthreads();
    if (threadIdx.x == 0) g_mask_kind = s_kind;   // 0 => int32
}

// ---------------------------------------------------------------------------
// Kernel 1: k[b,d] = sum_j W[d,j] * q[b,j] + bias[d]
// ---------------------------------------------------------------------------
__global__ __launch_bounds__(256) void key_kernel(const float* __restrict__ q,
                                                  const float* __restrict__ W,
                                                  const float* __restrict__ bias) {
    int b = blockIdx.x;
    __shared__ float4 qs[D / 4];
    for (int i = threadIdx.x; i < D / 4; i += blockDim.x)
        qs[i] = reinterpret_cast<const float4*>(q + b * D)[i];
    __syncthreads();

    for (int d = threadIdx.x; d < D; d += blockDim.x) {
        const float4* w = reinterpret_cast<const float4*>(W + (size_t)d * D);
        float acc = 0.f;
#pragma unroll 8
        for (int j = 0; j < D / 4; j++) {
            float4 wv = w[j];
            float4 qv = qs[j];
            acc = fmaf(wv.x, qv.x, acc);
            acc = fmaf(wv.y, qv.y, acc);
            acc = fmaf(wv.z, qv.z, acc);
            acc = fmaf(wv.w, qv.w, acc);
        }
        g_key[b * D + d] = acc + bias[d];
    }
}

// ---------------------------------------------------------------------------
// Kernel 2: per-warp online softmax over a 32-row strip, skipping masked rows.
// Lane l owns columns {4l + 128j : j=0..3} (4 x float4 = 16 floats).
// ---------------------------------------------------------------------------
__global__ __launch_bounds__(256) void partial_kernel(const float* __restrict__ A,
                                                      const void* __restrict__ mask_raw) {
    const int b     = blockIdx.x / NSPLIT;
    const int split = blockIdx.x % NSPLIT;
    const int warp  = threadIdx.x >> 5;
    const int lane  = threadIdx.x & 31;
    const int t0    = split * (T / NSPLIT) + warp * ROWS_PER_WARP;

    // One mask element per lane -> 32-row skip bitmap for this warp's strip
    const size_t midx = (size_t)(t0 + lane) * B + b;
    const int kind = g_mask_kind;   // uniform across grid
    bool masked;
    if (kind == 1)      masked = ((const unsigned char*)mask_raw)[midx] != 0;
    else if (kind == 0) masked = ((const int*)mask_raw)[midx] != 0;
    else                masked = ((const float*)mask_raw)[midx] != 0.f;
    unsigned mvote = __ballot_sync(0xffffffffu, masked);

    // k fragment for this lane's columns
    float4 kf[4];
    const float* kb = g_key + b * D + 4 * lane;
#pragma unroll
    for (int j = 0; j < 4; j++)
        kf[j] = *reinterpret_cast<const float4*>(kb + 128 * j);

    float m = -INFINITY, s = 0.f;
    float4 c[4];
#pragma unroll
    for (int j = 0; j < 4; j++) c[j] = make_float4(0.f, 0.f, 0.f, 0.f);

    const float* base = A + ((size_t)b * T + t0) * D + 4 * lane;

    for (int r = 0; r < ROWS_PER_WARP; r++) {
        if ((mvote >> r) & 1u) continue;   // masked row: weight 0, skip load
        const float* row = base + (size_t)r * D;
        float4 a[4];
#pragma unroll
        for (int j = 0; j < 4; j++)
            a[j] = *reinterpret_cast<const float4*>(row + 128 * j);

        // partial dot
        float p = 0.f;
#pragma unroll
        for (int j = 0; j < 4; j++) {
            p = fmaf(a[j].x, kf[j].x, p);
            p = fmaf(a[j].y, kf[j].y, p);
            p = fmaf(a[j].z, kf[j].z, p);
            p = fmaf(a[j].w, kf[j].w, p);
        }
        // warp-reduce the dot product
#pragma unroll
        for (int off = 16; off > 0; off >>= 1)
            p += __shfl_xor_sync(0xffffffffu, p, off);

        // online softmax update
        float mn    = fmaxf(m, p);
        float alpha = __expf(m - mn);   // m=-inf -> 0, kills stale state safely
        float w     = __expf(p - mn);
        s = s * alpha + w;
#pragma unroll
        for (int j = 0; j < 4; j++) {
            c[j].x = fmaf(w, a[j].x, c[j].x * alpha);
            c[j].y = fmaf(w, a[j].y, c[j].y * alpha);
            c[j].z = fmaf(w, a[j].z, c[j].z * alpha);
            c[j].w = fmaf(w, a[j].w, c[j].w * alpha);
        }
        m = mn;
    }

    const int pid = blockIdx.x * WARPS + warp;   // b*NPART + split*WARPS + warp
    if (lane == 0) {
        g_pm[pid] = m;
        g_ps[pid] = s;
    }
    float* pc = g_pc + (size_t)pid * D + 4 * lane;
#pragma unroll
    for (int j = 0; j < 4; j++)
        *reinterpret_cast<float4*>(pc + 128 * j) = c[j];
}

// ---------------------------------------------------------------------------
// Kernel 3: combine 128 partials per batch -> context[b, :]
// ---------------------------------------------------------------------------
__global__ __launch_bounds__(512) void reduce_kernel(float* __restrict__ out) {
    const int b   = blockIdx.x;
    const int tid = threadIdx.x;
    __shared__ float sm[NPART];   // m, then reused as scale
    __shared__ float ss[NPART];
    __shared__ float Msh, Ssh;

    if (tid < NPART) sm[tid] = g_pm[b * NPART + tid];
    __syncthreads();
    if (tid == 0) {
        float mm = -INFINITY;
        for (int i = 0; i < NPART; i++) mm = fmaxf(mm, sm[i]);
        Msh = mm;
    }
    __syncthreads();
    if (tid < NPART) {
        float mi = sm[tid];
        float sc = (mi == -INFINITY) ? 0.f : __expf(mi - Msh);
        sm[tid] = sc;
        ss[tid] = g_ps[b * NPART + tid] * sc;
    }
    __syncthreads();
    if (tid == 0) {
        float acc = 0.f;
        for (int i = 0; i < NPART; i++) acc += ss[i];
        Ssh = acc;
    }
    __syncthreads();

    // each thread owns one output column d = tid
    float acc = 0.f;
    const float* pc = g_pc + (size_t)b * NPART * D + tid;
#pragma unroll 8
    for (int i = 0; i < NPART; i++)
        acc = fmaf(pc[(size_t)i * D], sm[i], acc);
    out[b * D + tid] = acc / Ssh;
}

// ---------------------------------------------------------------------------
// Launch: inputs in metadata order: query, attend_to, mask, W, b
// ---------------------------------------------------------------------------
extern "C" void kernel_launch(void* const* d_in, const int* in_sizes, int n_in,
                              void* d_out, int out_size) {
    const float* q    = (const float*)d_in[0];   // [B, D]
    const float* A    = (const float*)d_in[1];   // [B, T, D]
    const void*  mask = d_in[2];                 // [T, B] bool-ish (dtype sniffed)
    const float* W    = (const float*)d_in[3];   // [D, D]
    const float* bias = (const float*)d_in[4];   // [D]
    float*       out  = (float*)d_out;           // [B, 1, D]

    detect_mask_kernel<<<1, 256>>>((const unsigned int*)mask);
    key_kernel<<<B, 256>>>(q, W, bias);
    partial_kernel<<<B * NSPLIT, WARPS * 32>>>(A, mask);
    reduce_kernel<<<B, D>>>(out);
}